// round 1
// baseline (speedup 1.0000x reference)
#include <cuda_runtime.h>
#include <cstdint>

// ---------------------------------------------------------------------------
// Problem constants
//   D = 640, NET1 = [640, 512, 64], NET3 = [640, 640, 512, 64, 512]
//   W_TOTAL = 640*640 + 640*512 + 512*64 + 64*512 = 802816
//   B_TOTAL = 640+512+64+512 = 1728
//   net2_w3 : [804544, 64]  (206 MB -- the entire cost of this problem)
// ---------------------------------------------------------------------------
#define W_TOTAL 802816L

// Scratch (device global: no allocation allowed in kernel_launch)
// offsets (floats):
//   inpt : 0     (640)
//   h0   : 640   (640)
//   h1   : 1280  (512)
//   h    : 1792  (64)
//   n1h  : 1856  (512)
//   x1   : 2368  (640)
//   x2v  : 3008  (512)
//   x3v  : 3520  (64)
__device__ __align__(16) float g_scratch[3584];

#define OFF_INPT 0
#define OFF_H0   640
#define OFF_H1   1280
#define OFF_H    1792
#define OFF_N1H  1856
#define OFF_X1   2368
#define OFF_X2V  3008
#define OFF_X3V  3520

// ---------------------------------------------------------------------------
// accurate-enough fast tanh: (e^{2x}-1)/(e^{2x}+1) via MUFU.EX2 + fast rcp.
// Inputs here are ~N(0, 2e-3) so relative error ~1e-4 << 1e-3 gate.
// ---------------------------------------------------------------------------
__device__ __forceinline__ float tanh_fast(float x) {
    float xc = fminf(fmaxf(x, -15.0f), 15.0f);
    float e  = __expf(2.0f * xc);
    return (e - 1.0f) * __fdividef(1.0f, e + 1.0f);
}

// ---------------------------------------------------------------------------
// prep: inpt = concat(x, prev_output, state)
// ---------------------------------------------------------------------------
__global__ void prep_kernel(const float* __restrict__ x,
                            const float* __restrict__ po,
                            const float* __restrict__ st) {
    int t = threadIdx.x;
    if (t < 64)       g_scratch[OFF_INPT + t] = x[t];
    else if (t < 128) g_scratch[OFF_INPT + t] = po[t - 64];
    else              g_scratch[OFF_INPT + t] = st[t - 128];
}

// ---------------------------------------------------------------------------
// small matvec: out[i] = act( W[i,:] . v + b[i] ),  one block per row
// ---------------------------------------------------------------------------
__global__ void matvec_kernel(const float* __restrict__ W,
                              const float* __restrict__ bias,
                              const float* __restrict__ v,
                              float* __restrict__ out,
                              int in_dim, int act) {
    __shared__ float sp[8];
    int i = blockIdx.x;
    const float* row = W + (size_t)i * in_dim;
    float p = 0.f;
    for (int k = threadIdx.x; k < in_dim; k += blockDim.x)
        p = fmaf(row[k], v[k], p);
    #pragma unroll
    for (int o = 16; o; o >>= 1) p += __shfl_xor_sync(0xffffffffu, p, o);
    int w = threadIdx.x >> 5;
    if ((threadIdx.x & 31) == 0) sp[w] = p;
    __syncthreads();
    if (threadIdx.x == 0) {
        float r = 0.f;
        int nw = blockDim.x >> 5;
        for (int j = 0; j < nw; j++) r += sp[j];
        r += bias[i];
        if (act) r = (r >= 0.f) ? r : 0.01f * r;
        out[i] = r;
    }
}

// ---------------------------------------------------------------------------
// Fused generate-and-apply layer of the hypernetwork-defined NET3.
//
//   vout[i] = act( sum_k g(wbase + i*in_dim + k) * vin[k]  +  gbias(i) )
//   g(m)     = 0.5 * tanh( w3[m,:64] . h + b3[m] )
//   gbias(i) = 0.5 * tanh( w3[W_TOTAL+bb+i,:64] . h + b3[W_TOTAL+bb+i] )
//
// One block per output row i. Each warp handles TWO generated elements per
// iteration with a single coalesced float4 load (512B = rows k, k+1):
//   lane l (l<16): row k,    cols 4*(l&15)..+3
//   lane l (>=16): row k+1,  same cols
// Butterfly (xor 1,2,4,8) reduces within each 16-lane half.
// ---------------------------------------------------------------------------
__global__ void gen_layer_kernel(const float* __restrict__ w3,
                                 const float* __restrict__ b3,
                                 const float* __restrict__ h,
                                 const float* __restrict__ vin,
                                 float* __restrict__ vout,
                                 int in_dim, long wbase, long bb, int act) {
    __shared__ float s_vin[640];
    __shared__ float s_part[16];
    int tid  = threadIdx.x;
    int i    = blockIdx.x;
    int lane = tid & 31;
    int w    = tid >> 5;
    int nwarp = blockDim.x >> 5;
    int q    = lane & 15;
    int half = lane >> 4;

    for (int k = tid; k < in_dim; k += blockDim.x) s_vin[k] = vin[k];
    float4 hreg = *(const float4*)(h + 4 * q);
    __syncthreads();

    long rowbase = wbase + (long)i * in_dim;
    float acc = 0.f;
    int stride = 2 * nwarp;
    #pragma unroll 4
    for (int k = 2 * w; k < in_dim; k += stride) {
        const float4* p = (const float4*)(w3 + (rowbase + k) * 64);
        float4 a = p[lane];                           // 512B coalesced: rows k, k+1
        float s = a.x * hreg.x;
        s = fmaf(a.y, hreg.y, s);
        s = fmaf(a.z, hreg.z, s);
        s = fmaf(a.w, hreg.w, s);
        s += __shfl_xor_sync(0xffffffffu, s, 1);
        s += __shfl_xor_sync(0xffffffffu, s, 2);
        s += __shfl_xor_sync(0xffffffffu, s, 4);
        s += __shfl_xor_sync(0xffffffffu, s, 8);      // per-half dot(w3-row, h)
        s += __ldg(&b3[rowbase + k + half]);
        float g = 0.5f * tanh_fast(s);
        acc = fmaf(g, s_vin[k + half], acc);
    }
    // combine the two halves (each half's acc is replicated across its 16 lanes)
    acc += __shfl_xor_sync(0xffffffffu, acc, 16);
    if (lane == 0) s_part[w] = acc;
    __syncthreads();

    if (w == 0) {
        float t = (lane < nwarp) ? s_part[lane] : 0.f;
        #pragma unroll
        for (int o = 8; o; o >>= 1) t += __shfl_xor_sync(0xffffffffu, t, o);
        // generated bias for row i
        long mb = W_TOTAL + bb + i;
        const float* br = w3 + mb * 64;
        float sb = br[lane] * h[lane] + br[lane + 32] * h[lane + 32];
        #pragma unroll
        for (int o = 16; o; o >>= 1) sb += __shfl_xor_sync(0xffffffffu, sb, o);
        sb += b3[mb];
        float gb = 0.5f * tanh_fast(sb);
        if (lane == 0) {
            float r = t + gb;
            if (act) r = (r >= 0.f) ? r : 0.01f * r;
            vout[i] = r;
        }
    }
}

// ---------------------------------------------------------------------------
// launch
// ---------------------------------------------------------------------------
extern "C" void kernel_launch(void* const* d_in, const int* in_sizes, int n_in,
                              void* d_out, int out_size) {
    const float* x    = (const float*)d_in[0];
    const float* po   = (const float*)d_in[1];
    const float* st   = (const float*)d_in[2];
    const float* n1w0 = (const float*)d_in[3];
    const float* n1b0 = (const float*)d_in[4];
    const float* n1w1 = (const float*)d_in[5];
    const float* n1b1 = (const float*)d_in[6];
    const float* n2w0 = (const float*)d_in[7];
    const float* n2b0 = (const float*)d_in[8];
    const float* n2w1 = (const float*)d_in[9];
    const float* n2b1 = (const float*)d_in[10];
    const float* n2w2 = (const float*)d_in[11];
    const float* n2b2 = (const float*)d_in[12];
    const float* n2w3 = (const float*)d_in[13];
    const float* n2b3 = (const float*)d_in[14];
    float* out = (float*)d_out;

    float* scratch = nullptr;
    cudaGetSymbolAddress((void**)&scratch, g_scratch);
    float* inpt = scratch + OFF_INPT;
    float* h0   = scratch + OFF_H0;
    float* h1   = scratch + OFF_H1;
    float* hh   = scratch + OFF_H;
    float* n1h  = scratch + OFF_N1H;
    float* x1   = scratch + OFF_X1;
    float* x2v  = scratch + OFF_X2V;
    float* x3v  = scratch + OFF_X3V;

    // inpt = concat(x, prev_output, state)
    prep_kernel<<<1, 640>>>(x, po, st);

    // net1 path -> out[0:64]
    matvec_kernel<<<512, 256>>>(n1w0, n1b0, inpt, n1h, 640, 1);
    matvec_kernel<<<64,  256>>>(n1w1, n1b1, n1h,  out, 512, 0);

    // net2 trunk -> h (64)
    matvec_kernel<<<640, 256>>>(n2w0, n2b0, inpt, h0, 640, 1);
    matvec_kernel<<<512, 256>>>(n2w1, n2b1, h0,   h1, 640, 1);
    matvec_kernel<<<64,  256>>>(n2w2, n2b2, h1,   hh, 512, 1);

    // hypernetwork-defined NET3, weights generated on the fly from n2w3 (206MB)
    // layer 1: 640x640, wbase=0,       bb=0
    gen_layer_kernel<<<640, 256>>>(n2w3, n2b3, hh, inpt, x1, 640, 0L,      0L,    1);
    // layer 2: 512x640, wbase=409600,  bb=640
    gen_layer_kernel<<<512, 256>>>(n2w3, n2b3, hh, x1,  x2v, 640, 409600L, 640L,  1);
    // layer 3: 64x512,  wbase=737280,  bb=1152
    gen_layer_kernel<<<64,  512>>>(n2w3, n2b3, hh, x2v, x3v, 512, 737280L, 1152L, 1);
    // layer 4: 512x64,  wbase=770048,  bb=1216, no activation -> new_state
    gen_layer_kernel<<<512, 512>>>(n2w3, n2b3, hh, x3v, out + 64, 64, 770048L, 1216L, 0);
}

// round 2
// speedup vs baseline: 1.7929x; 1.7929x over previous
#include <cuda_runtime.h>
#include <cstdint>

// ---------------------------------------------------------------------------
// D = 640, NET1 = [640, 512, 64], NET3 = [640, 640, 512, 64, 512]
// W_TOTAL = 802816, net2_w3 : [804544, 64] fp32 = 206MB  (the whole problem)
// ---------------------------------------------------------------------------
#define W_TOTAL 802816L

// scratch offsets (floats):
//  n1h: 0 (512) | h0: 512 (640) | h1: 1152 (512) | hh: 1664 (64)
//  x1: 1728 (640) | x2v: 2368 (512) | x3v: 2880 (64)
__device__ __align__(16) float g_scratch[3584];
#define OFF_N1H 0
#define OFF_H0  512
#define OFF_H1  1152
#define OFF_HH  1664
#define OFF_X1  1728
#define OFF_X2V 2368
#define OFF_X3V 2880

// accurate fast tanh: (e^{2x}-1)/(e^{2x}+1); inputs tiny -> rel err ~1e-7 level
__device__ __forceinline__ float tanh_fast(float x) {
    float xc = fminf(fmaxf(x, -15.0f), 15.0f);
    float e  = __expf(2.0f * xc);
    return (e - 1.0f) * __fdividef(1.0f, e + 1.0f);
}

// ---------------------------------------------------------------------------
// Fused small matvec: two independent GEMVs in one launch, warp-per-row.
// Optionally reads the input vector as concat(x, prev_output, state).
// ---------------------------------------------------------------------------
__global__ void __launch_bounds__(256) mv_dual(
    const float* __restrict__ WA, const float* __restrict__ bA,
    const float* __restrict__ vA, float* __restrict__ oA,
    int rowsA, int inA, int actA, int blkA,
    const float* __restrict__ WB, const float* __restrict__ bB,
    const float* __restrict__ vB, float* __restrict__ oB,
    int rowsB, int inB, int actB,
    const float* __restrict__ cx, const float* __restrict__ cpo,
    const float* __restrict__ cst, int concat)
{
    __shared__ float s_v[640];
    const float* W; const float* bb_; const float* v; float* o;
    int rows, in, act, rbase;
    if ((int)blockIdx.x < blkA) {
        W = WA; bb_ = bA; v = vA; o = oA; rows = rowsA; in = inA; act = actA;
        rbase = blockIdx.x * 8;
    } else {
        W = WB; bb_ = bB; v = vB; o = oB; rows = rowsB; in = inB; act = actB;
        rbase = (blockIdx.x - blkA) * 8;
    }
    for (int k = threadIdx.x; k < in; k += 256) {
        float x;
        if (concat) x = (k < 64) ? cx[k] : (k < 128 ? cpo[k - 64] : cst[k - 128]);
        else        x = v[k];
        s_v[k] = x;
    }
    __syncthreads();
    int w = threadIdx.x >> 5, lane = threadIdx.x & 31;
    int r = rbase + w;
    if (r < rows) {
        const float* row = W + (size_t)r * in;
        float p = 0.f;
        for (int k = lane; k < in; k += 32) p = fmaf(row[k], s_v[k], p);
        #pragma unroll
        for (int off = 16; off; off >>= 1) p += __shfl_xor_sync(0xffffffffu, p, off);
        if (lane == 0) {
            p += bb_[r];
            if (act) p = (p >= 0.f) ? p : 0.01f * p;
            o[r] = p;
        }
    }
}

// ---------------------------------------------------------------------------
// Fused generate-and-apply NET3 layer.
//   vout[i] = act( sum_k g(wbase + i*IN_DIM + k) * vin[k] + gbias(i) )
//   g(m)    = 0.5 * tanh( w3[m,:64] . h + b3[m] )
//
// 8 lanes per generated element: each LDG.128 covers 4 rows x 128B of fully
// contiguous, line-aligned data (optimal L1 wavefronts). 3 SHFL + 1 tanh per
// 4 elements. h lives in 2 float4 registers per lane. Loop fully unrolled
// (compile-time IN_DIM) for deep MLP.
// ---------------------------------------------------------------------------
template<int IN_DIM, int ACT, int CONCAT>
__global__ void __launch_bounds__(256) gen_layer(
    const float* __restrict__ w3, const float* __restrict__ b3,
    const float* __restrict__ h,  const float* __restrict__ vin,
    const float* __restrict__ cx, const float* __restrict__ cpo,
    const float* __restrict__ cst,
    float* __restrict__ vout, long wbase, long bb)
{
    __shared__ float s_vin[IN_DIM];
    __shared__ float s_b3[IN_DIM];
    __shared__ float s_part[8];
    const int tid  = threadIdx.x;
    const int i    = blockIdx.x;
    const int lane = tid & 31;
    const int w    = tid >> 5;
    const int grp  = lane >> 3;      // which of 4 rows in this instr
    const int lp   = lane & 7;       // position within row (8 lanes/row)
    const long rowbase = wbase + (long)i * IN_DIM;

    for (int k = tid; k < IN_DIM; k += 256) {
        float v;
        if (CONCAT) v = (k < 64) ? cx[k] : (k < 128 ? cpo[k - 64] : cst[k - 128]);
        else        v = vin[k];
        s_vin[k] = v;
        s_b3[k]  = b3[rowbase + k];
    }
    const float4 hr0 = *(const float4*)(h + lp * 4);
    const float4 hr1 = *(const float4*)(h + lp * 4 + 32);
    __syncthreads();

    float acc = 0.f;
    #pragma unroll
    for (int t = 0; t < IN_DIM / 32; t++) {
        const int r = 4 * w + 32 * t + grp;
        const float4* p = (const float4*)(w3 + (rowbase + r) * 64);
        float4 a0 = p[lp];       // bytes [lp*16 .. +16) of row r (first 128B)
        float4 a1 = p[lp + 8];   // second 128B half of row r
        float s = a0.x * hr0.x;
        s = fmaf(a0.y, hr0.y, s);
        s = fmaf(a0.z, hr0.z, s);
        s = fmaf(a0.w, hr0.w, s);
        s = fmaf(a1.x, hr1.x, s);
        s = fmaf(a1.y, hr1.y, s);
        s = fmaf(a1.z, hr1.z, s);
        s = fmaf(a1.w, hr1.w, s);
        s += __shfl_xor_sync(0xffffffffu, s, 1);
        s += __shfl_xor_sync(0xffffffffu, s, 2);
        s += __shfl_xor_sync(0xffffffffu, s, 4);   // per-8-lane dot(w3row, h)
        s += s_b3[r];
        float g = 0.5f * tanh_fast(s);
        acc = fmaf(g, s_vin[r], acc);
    }
    // acc replicated within each 8-lane group; sum the 4 groups
    acc += __shfl_xor_sync(0xffffffffu, acc, 8);
    acc += __shfl_xor_sync(0xffffffffu, acc, 16);
    if (lane == 0) s_part[w] = acc;
    __syncthreads();

    if (w == 0) {
        float t8 = (lane < 8) ? s_part[lane] : 0.f;
        t8 += __shfl_xor_sync(0xffffffffu, t8, 1);
        t8 += __shfl_xor_sync(0xffffffffu, t8, 2);
        t8 += __shfl_xor_sync(0xffffffffu, t8, 4);
        // generated bias for output row i
        const long mb = W_TOTAL + bb + i;
        const float* br = w3 + mb * 64;
        float sb = br[lane] * h[lane] + br[lane + 32] * h[lane + 32];
        #pragma unroll
        for (int off = 16; off; off >>= 1) sb += __shfl_xor_sync(0xffffffffu, sb, off);
        sb += b3[mb];
        float gb = 0.5f * tanh_fast(sb);
        if (lane == 0) {
            float r = t8 + gb;
            if (ACT) r = (r >= 0.f) ? r : 0.01f * r;
            vout[i] = r;
        }
    }
}

// ---------------------------------------------------------------------------
extern "C" void kernel_launch(void* const* d_in, const int* in_sizes, int n_in,
                              void* d_out, int out_size) {
    const float* x    = (const float*)d_in[0];
    const float* po   = (const float*)d_in[1];
    const float* st   = (const float*)d_in[2];
    const float* n1w0 = (const float*)d_in[3];
    const float* n1b0 = (const float*)d_in[4];
    const float* n1w1 = (const float*)d_in[5];
    const float* n1b1 = (const float*)d_in[6];
    const float* n2w0 = (const float*)d_in[7];
    const float* n2b0 = (const float*)d_in[8];
    const float* n2w1 = (const float*)d_in[9];
    const float* n2b1 = (const float*)d_in[10];
    const float* n2w2 = (const float*)d_in[11];
    const float* n2b2 = (const float*)d_in[12];
    const float* n2w3 = (const float*)d_in[13];
    const float* n2b3 = (const float*)d_in[14];
    float* out = (float*)d_out;

    float* sc = nullptr;
    cudaGetSymbolAddress((void**)&sc, g_scratch);
    float* n1h = sc + OFF_N1H;
    float* h0  = sc + OFF_H0;
    float* h1  = sc + OFF_H1;
    float* hh  = sc + OFF_HH;
    float* x1  = sc + OFF_X1;
    float* x2v = sc + OFF_X2V;
    float* x3v = sc + OFF_X3V;

    // K1: n1w0 (512x640, leaky -> n1h)  ||  n2w0 (640x640, leaky -> h0), concat input
    mv_dual<<<64 + 80, 256>>>(n1w0, n1b0, nullptr, n1h, 512, 640, 1, 64,
                              n2w0, n2b0, nullptr, h0,  640, 640, 1,
                              x, po, st, 1);
    // K2: n1w1 (64x512 -> out[0:64], no act)  ||  n2w1 (512x640, leaky -> h1)
    mv_dual<<<8 + 64, 256>>>(n1w1, n1b1, n1h, out, 64, 512, 0, 8,
                             n2w1, n2b1, h0,  h1, 512, 640, 1,
                             nullptr, nullptr, nullptr, 0);
    // K3: n2w2 (64x512, leaky -> hh)
    mv_dual<<<8, 256>>>(n2w2, n2b2, h1, hh, 64, 512, 1, 8,
                        nullptr, nullptr, nullptr, nullptr, 0, 0, 0,
                        nullptr, nullptr, nullptr, 0);

    // Hypernetwork-defined NET3 (fused generate-and-apply)
    gen_layer<640, 1, 1><<<640, 256>>>(n2w3, n2b3, hh, nullptr, x, po, st,
                                       x1, 0L, 0L);
    gen_layer<640, 1, 0><<<512, 256>>>(n2w3, n2b3, hh, x1, nullptr, nullptr, nullptr,
                                       x2v, 409600L, 640L);
    gen_layer<512, 1, 0><<<64, 256>>>(n2w3, n2b3, hh, x2v, nullptr, nullptr, nullptr,
                                      x3v, 737280L, 1152L);
    gen_layer<64, 0, 0><<<512, 256>>>(n2w3, n2b3, hh, x3v, nullptr, nullptr, nullptr,
                                      out + 64, 770048L, 1216L);
}

// round 3
// speedup vs baseline: 1.9554x; 1.0906x over previous
#include <cuda_runtime.h>
#include <cstdint>

// ---------------------------------------------------------------------------
// D = 640, NET1 = [640, 512, 64], NET3 = [640, 640, 512, 64, 512]
// W_TOTAL = 802816, net2_w3 : [804544, 64] fp32 = 206MB  (the whole problem)
// ---------------------------------------------------------------------------
#define W_TOTAL 802816L

// scratch offsets (floats):
//  n1h: 0 (512) | h0: 512 (640) | h1: 1152 (512) | hh: 1664 (64)
//  x1: 1728 (640) | x2v: 2368 (512) | p3: 2880 (256)
__device__ __align__(16) float g_scratch[4096];
#define OFF_N1H 0
#define OFF_H0  512
#define OFF_H1  1152
#define OFF_HH  1664
#define OFF_X1  1728
#define OFF_X2V 2368
#define OFF_P3  2880

// accurate fast tanh: (e^{2x}-1)/(e^{2x}+1); inputs tiny -> rel err ~1e-7 level
__device__ __forceinline__ float tanh_fast(float x) {
    float xc = fminf(fmaxf(x, -15.0f), 15.0f);
    float e  = __expf(2.0f * xc);
    return (e - 1.0f) * __fdividef(1.0f, e + 1.0f);
}

// ---------------------------------------------------------------------------
// Fused small matvec: two independent GEMVs in one launch, warp-per-row.
// ---------------------------------------------------------------------------
__global__ void __launch_bounds__(256) mv_dual(
    const float* __restrict__ WA, const float* __restrict__ bA,
    const float* __restrict__ vA, float* __restrict__ oA,
    int rowsA, int inA, int actA, int blkA,
    const float* __restrict__ WB, const float* __restrict__ bB,
    const float* __restrict__ vB, float* __restrict__ oB,
    int rowsB, int inB, int actB,
    const float* __restrict__ cx, const float* __restrict__ cpo,
    const float* __restrict__ cst, int concat)
{
    __shared__ float s_v[640];
    const float* W; const float* bb_; const float* v; float* o;
    int rows, in, act, rbase;
    if ((int)blockIdx.x < blkA) {
        W = WA; bb_ = bA; v = vA; o = oA; rows = rowsA; in = inA; act = actA;
        rbase = blockIdx.x * 8;
    } else {
        W = WB; bb_ = bB; v = vB; o = oB; rows = rowsB; in = inB; act = actB;
        rbase = (blockIdx.x - blkA) * 8;
    }
    for (int k = threadIdx.x; k < in; k += 256) {
        float x;
        if (concat) x = (k < 64) ? cx[k] : (k < 128 ? cpo[k - 64] : cst[k - 128]);
        else        x = v[k];
        s_v[k] = x;
    }
    __syncthreads();
    int w = threadIdx.x >> 5, lane = threadIdx.x & 31;
    int r = rbase + w;
    if (r < rows) {
        const float* row = W + (size_t)r * in;
        float p = 0.f;
        for (int k = lane; k < in; k += 32) p = fmaf(row[k], s_v[k], p);
        #pragma unroll
        for (int off = 16; off; off >>= 1) p += __shfl_xor_sync(0xffffffffu, p, off);
        if (lane == 0) {
            p += bb_[r];
            if (act) p = (p >= 0.f) ? p : 0.01f * p;
            o[r] = p;
        }
    }
}

// ---------------------------------------------------------------------------
// Fused generate-and-apply NET3 layer.
//   vout[row] = act( sum_k g(wbase + row*IN_DIM + k) * vin[k] + gbias(row) )
//   g(m)      = 0.5 * tanh( w3[m,:64] . h + b3[m] )
//
// 512-thread blocks (4 blocks/SM -> 64 warps/SM, full occupancy).
// 8 lanes per generated element: each LDG.128 covers 4 rows x 128B contiguous.
// SPLIT>1: this block handles a LEN=IN_DIM/SPLIT chunk of the row and writes a
//   partial sum (chunk 0 folds in the generated bias); activation deferred.
// COMB4: input vector is 4-way partials from the previous SPLIT=4 layer;
//   combine + leaky applied while staging into smem.
// ---------------------------------------------------------------------------
template<int IN_DIM, int SPLIT, int ACT, int CONCAT, int COMB4>
__global__ void __launch_bounds__(512, 4) gen_layer(
    const float* __restrict__ w3, const float* __restrict__ b3,
    const float* __restrict__ h,  const float* __restrict__ vin,
    const float* __restrict__ cx, const float* __restrict__ cpo,
    const float* __restrict__ cst,
    float* __restrict__ vout, long wbase, long bb)
{
    constexpr int LEN = IN_DIM / SPLIT;
    static_assert(LEN % 64 == 0, "LEN must be multiple of 64");
    __shared__ float s_vin[LEN];
    __shared__ float s_b3[LEN];
    __shared__ float s_part[16];
    const int tid  = threadIdx.x;
    const int row  = (SPLIT == 1) ? blockIdx.x : (blockIdx.x / SPLIT);
    const int chunk= (SPLIT == 1) ? 0 : (blockIdx.x % SPLIT);
    const int lane = tid & 31;
    const int w    = tid >> 5;
    const int grp  = lane >> 3;
    const int lp   = lane & 7;
    const long rowbase = wbase + (long)row * IN_DIM + (long)chunk * LEN;

    for (int k = tid; k < LEN; k += 512) {
        float v;
        if (CONCAT) {
            v = (k < 64) ? cx[k] : (k < 128 ? cpo[k - 64] : cst[k - 128]);
        } else if (COMB4) {
            float p = vin[4 * k] + vin[4 * k + 1] + vin[4 * k + 2] + vin[4 * k + 3];
            v = (p >= 0.f) ? p : 0.01f * p;   // deferred leaky from the split layer
        } else {
            v = vin[chunk * LEN + k];
        }
        s_vin[k] = v;
        s_b3[k]  = b3[rowbase + k];
    }
    const float4 hr0 = *(const float4*)(h + lp * 4);
    const float4 hr1 = *(const float4*)(h + lp * 4 + 32);
    __syncthreads();

    float acc = 0.f;
    #pragma unroll
    for (int t = 0; t < LEN / 64; t++) {
        const int r = 64 * t + 4 * w + grp;
        const float4* p = (const float4*)(w3 + (rowbase + r) * 64);
        float4 a0 = p[lp];
        float4 a1 = p[lp + 8];
        float s = a0.x * hr0.x;
        s = fmaf(a0.y, hr0.y, s);
        s = fmaf(a0.z, hr0.z, s);
        s = fmaf(a0.w, hr0.w, s);
        s = fmaf(a1.x, hr1.x, s);
        s = fmaf(a1.y, hr1.y, s);
        s = fmaf(a1.z, hr1.z, s);
        s = fmaf(a1.w, hr1.w, s);
        s += __shfl_xor_sync(0xffffffffu, s, 1);
        s += __shfl_xor_sync(0xffffffffu, s, 2);
        s += __shfl_xor_sync(0xffffffffu, s, 4);   // per-8-lane dot(w3row, h)
        s += s_b3[r];
        float g = 0.5f * tanh_fast(s);
        acc = fmaf(g, s_vin[r], acc);
    }
    acc += __shfl_xor_sync(0xffffffffu, acc, 8);
    acc += __shfl_xor_sync(0xffffffffu, acc, 16);
    if (lane == 0) s_part[w] = acc;
    __syncthreads();

    if (w == 0) {
        float t16 = (lane < 16) ? s_part[lane] : 0.f;
        t16 += __shfl_xor_sync(0xffffffffu, t16, 1);
        t16 += __shfl_xor_sync(0xffffffffu, t16, 2);
        t16 += __shfl_xor_sync(0xffffffffu, t16, 4);
        t16 += __shfl_xor_sync(0xffffffffu, t16, 8);
        float gb = 0.f;
        if (SPLIT == 1 || chunk == 0) {
            const long mb = W_TOTAL + bb + row;
            const float* br = w3 + mb * 64;
            float sb = br[lane] * h[lane] + br[lane + 32] * h[lane + 32];
            #pragma unroll
            for (int off = 16; off; off >>= 1)
                sb += __shfl_xor_sync(0xffffffffu, sb, off);
            sb += b3[mb];
            gb = 0.5f * tanh_fast(sb);
        }
        if (lane == 0) {
            float r = t16 + gb;
            if (SPLIT == 1) {
                if (ACT) r = (r >= 0.f) ? r : 0.01f * r;
                vout[row] = r;
            } else {
                vout[row * SPLIT + chunk] = r;   // partial; act deferred
            }
        }
    }
}

// ---------------------------------------------------------------------------
extern "C" void kernel_launch(void* const* d_in, const int* in_sizes, int n_in,
                              void* d_out, int out_size) {
    const float* x    = (const float*)d_in[0];
    const float* po   = (const float*)d_in[1];
    const float* st   = (const float*)d_in[2];
    const float* n1w0 = (const float*)d_in[3];
    const float* n1b0 = (const float*)d_in[4];
    const float* n1w1 = (const float*)d_in[5];
    const float* n1b1 = (const float*)d_in[6];
    const float* n2w0 = (const float*)d_in[7];
    const float* n2b0 = (const float*)d_in[8];
    const float* n2w1 = (const float*)d_in[9];
    const float* n2b1 = (const float*)d_in[10];
    const float* n2w2 = (const float*)d_in[11];
    const float* n2b2 = (const float*)d_in[12];
    const float* n2w3 = (const float*)d_in[13];
    const float* n2b3 = (const float*)d_in[14];
    float* out = (float*)d_out;

    float* sc = nullptr;
    cudaGetSymbolAddress((void**)&sc, g_scratch);
    float* n1h = sc + OFF_N1H;
    float* h0  = sc + OFF_H0;
    float* h1  = sc + OFF_H1;
    float* hh  = sc + OFF_HH;
    float* x1  = sc + OFF_X1;
    float* x2v = sc + OFF_X2V;
    float* p3  = sc + OFF_P3;

    // K1: n1w0 (512x640, leaky -> n1h)  ||  n2w0 (640x640, leaky -> h0), concat input
    mv_dual<<<64 + 80, 256>>>(n1w0, n1b0, nullptr, n1h, 512, 640, 1, 64,
                              n2w0, n2b0, nullptr, h0,  640, 640, 1,
                              x, po, st, 1);
    // K2: n1w1 (64x512 -> out[0:64], no act)  ||  n2w1 (512x640, leaky -> h1)
    mv_dual<<<8 + 64, 256>>>(n1w1, n1b1, n1h, out, 64, 512, 0, 8,
                             n2w1, n2b1, h0,  h1, 512, 640, 1,
                             nullptr, nullptr, nullptr, 0);
    // K3: n2w2 (64x512, leaky -> hh)
    mv_dual<<<8, 256>>>(n2w2, n2b2, h1, hh, 64, 512, 1, 8,
                        nullptr, nullptr, nullptr, nullptr, 0, 0, 0,
                        nullptr, nullptr, nullptr, 0);

    // Hypernetwork-defined NET3 (fused generate-and-apply), 512-thread blocks
    // layer 1: 640x640, wbase=0, bb=0, concat input
    gen_layer<640, 1, 1, 1, 0><<<640, 512>>>(n2w3, n2b3, hh, nullptr, x, po, st,
                                             x1, 0L, 0L);
    // layer 2: 512x640, wbase=409600, bb=640
    gen_layer<640, 1, 1, 0, 0><<<512, 512>>>(n2w3, n2b3, hh, x1, nullptr, nullptr,
                                             nullptr, x2v, 409600L, 640L);
    // layer 3: 64x512 split 4-way -> partials p3[256] (act deferred)
    gen_layer<512, 4, 1, 0, 0><<<256, 512>>>(n2w3, n2b3, hh, x2v, nullptr, nullptr,
                                             nullptr, p3, 737280L, 1152L);
    // layer 4: 512x64, combines p3 (+leaky) on input, no act -> new_state
    gen_layer<64, 1, 0, 0, 1><<<512, 512>>>(n2w3, n2b3, hh, p3, nullptr, nullptr,
                                            nullptr, out + 64, 770048L, 1216L);
}